// round 6
// baseline (speedup 1.0000x reference)
#include <cuda_runtime.h>
#include <cuda_bf16.h>
#include <cstdint>
#include <math.h>

#define N_PTS 8192
#define DIM   2048
#define NCLS  751
#define KNN   6
#define CAND  16
#define GIN_ONE_PLUS_EPS 1.3f
#define BN_EPS 1e-5f

// ---------------- scratch ----------------------------------------------------
__device__ float g_xn [(size_t)N_PTS * DIM];
__device__ unsigned short g_xh [(size_t)N_PTS * DIM];     // bf16 of xn
__device__ float g_sim[(size_t)N_PTS * N_PTS];
__device__ int   g_cand[(size_t)N_PTS * CAND];
__device__ int   g_idx[(size_t)N_PTS * KNN];
__device__ float g_h0 [(size_t)N_PTS * DIM];
__device__ float g_h1 [(size_t)N_PTS * DIM];
__device__ float g_h2 [(size_t)N_PTS * DIM];
__device__ float g_hn [(size_t)N_PTS * DIM];
__device__ unsigned short g_sh [(size_t)N_PTS * DIM];     // activation split hi
__device__ unsigned short g_sl [(size_t)N_PTS * DIM];     // activation split lo
__device__ unsigned short g_w1h[(size_t)DIM * DIM], g_w1l[(size_t)DIM * DIM];
__device__ unsigned short g_w2h[(size_t)DIM * DIM], g_w2l[(size_t)DIM * DIM];
__device__ unsigned short g_wch[(size_t)NCLS * DIM], g_wcl[(size_t)NCLS * DIM];
__device__ float g_scale[DIM];
__device__ float g_shift[DIM];

// ---------------- helpers ----------------------------------------------------
__device__ __forceinline__ uint32_t smem_to_u32(const void* p) {
    uint32_t a;
    asm("{ .reg .u64 t; cvta.to.shared.u64 t, %1; cvt.u32.u64 %0, t; }" : "=r"(a) : "l"(p));
    return a;
}

__device__ __forceinline__ void cp_async16(uint32_t dst, const void* src, int valid) {
    asm volatile("cp.async.cg.shared.global [%0], [%1], 16, %2;"
                 :: "r"(dst), "l"(src), "r"(valid ? 16 : 0) : "memory");
}
__device__ __forceinline__ void cp_commit() {
    asm volatile("cp.async.commit_group;" ::: "memory");
}
template <int N>
__device__ __forceinline__ void cp_wait() {
    asm volatile("cp.async.wait_group %0;" :: "n"(N) : "memory");
}

__device__ __forceinline__ void ldm_x4(uint32_t* r, uint32_t addr) {
    asm volatile("ldmatrix.sync.aligned.m8n8.x4.shared.b16 {%0,%1,%2,%3}, [%4];"
                 : "=r"(r[0]), "=r"(r[1]), "=r"(r[2]), "=r"(r[3]) : "r"(addr));
}

__device__ __forceinline__ void mma16816(float* d, const uint32_t* a, uint32_t b0, uint32_t b1) {
    asm volatile("mma.sync.aligned.m16n8k16.row.col.f32.bf16.bf16.f32 "
                 "{%0,%1,%2,%3}, {%4,%5,%6,%7}, {%8,%9}, {%0,%1,%2,%3};"
                 : "+f"(d[0]), "+f"(d[1]), "+f"(d[2]), "+f"(d[3])
                 : "r"(a[0]), "r"(a[1]), "r"(a[2]), "r"(a[3]), "r"(b0), "r"(b1));
}

// ---------------- bf16 mma.sync GEMM: C[M,Nc] = A[M,K] * B[Nc,K]^T ----------
// CTA tile 128x256, BK=64, 256 thr (8 warps 2x4, warp tile 64x64), 3-stage
// cp.async pipeline, XOR-swizzled smem, ldmatrix.x4 operands.
// three=1: acc = Ah*Bh + Ah*Bl + Al*Bh (hi/lo bf16 split, fp32 accum).
// symm=1 : compute iff 2*bx <= by; mirror tile stored via smem transpose.
#define STAGE_B 49152
#define SMEM_GEMM (3 * STAGE_B)    // 147456; transpose stage needs 131584

__global__ __launch_bounds__(256, 1)
void gemm_mma(const __nv_bfloat16* __restrict__ Ah, const __nv_bfloat16* __restrict__ Al,
              const __nv_bfloat16* __restrict__ Bh, const __nv_bfloat16* __restrict__ Bl,
              float* __restrict__ C, int M, int Nc, int Kd,
              const float* __restrict__ bias, int relu, int three, int symm)
{
    const int bx = blockIdx.x, by = blockIdx.y;
    if (symm && 2 * bx > by) return;

    extern __shared__ char smem[];
    const uint32_t sb = smem_to_u32(smem);
    const int tid = threadIdx.x;
    const int lane = tid & 31;
    const int wid = tid >> 5;
    const int wm = wid >> 2;         // 0..1  (M dir, 64 rows)
    const int wn = wid & 3;          // 0..3  (N dir, 64 cols)
    const int wRow = wm * 64, wCol = wn * 64;

    const int rowBase = by * 128;
    const int colBase = bx * 256;
    const int kcount = Kd / 64;
    const int nchunk = (three ? 3 : 1) * kcount;

    float acc[4][8][4];
#pragma unroll
    for (int i = 0; i < 4; ++i)
#pragma unroll
        for (int j = 0; j < 8; ++j)
#pragma unroll
            for (int q = 0; q < 4; ++q) acc[i][j][q] = 0.f;

    // ---- async chunk loader (A: 16KB, B: 32KB per stage) ----
    auto load_chunk = [&](int c) {
        const int pass = three ? (c / kcount) : 0;
        const int k0 = (three ? (c % kcount) : c) * 64;
        const __nv_bfloat16* As = (pass == 2) ? Al : Ah;
        const __nv_bfloat16* Bs = (pass == 1) ? Bl : Bh;
        const uint32_t base = sb + (uint32_t)(c % 3) * STAGE_B;
#pragma unroll
        for (int i = 0; i < 4; ++i) {              // A tile: 1024 x 16B
            const int u = tid + i * 256;
            const int r = u >> 3, ku = u & 7;
            const int grow = rowBase + r;
            cp_async16(base + (uint32_t)(r * 8 + (ku ^ (r & 7))) * 16,
                       As + (size_t)grow * Kd + k0 + ku * 8, grow < M);
        }
#pragma unroll
        for (int i = 0; i < 8; ++i) {              // B tile: 2048 x 16B
            const int u = tid + i * 256;
            const int r = u >> 3, ku = u & 7;
            const int grow = colBase + r;
            cp_async16(base + 16384u + (uint32_t)(r * 8 + (ku ^ (r & 7))) * 16,
                       Bs + (size_t)grow * Kd + k0 + ku * 8, grow < Nc);
        }
        cp_commit();
    };

    load_chunk(0);
    load_chunk(1);

    for (int c = 0; c < nchunk; ++c) {
        cp_wait<1>();
        __syncthreads();
        if (c + 2 < nchunk) load_chunk(c + 2);

        const uint32_t base = sb + (uint32_t)(c % 3) * STAGE_B;
#pragma unroll
        for (int s = 0; s < 4; ++s) {              // four k16 steps
            uint32_t a[4][4];
#pragma unroll
            for (int i = 0; i < 4; ++i) {
                const int r = wRow + i * 16 + (lane & 15);
                const int ku = s * 2 + (lane >> 4);
                ldm_x4(a[i], base + (uint32_t)(r * 8 + (ku ^ (r & 7))) * 16);
            }
            uint32_t bf[4][4];
#pragma unroll
            for (int j = 0; j < 4; ++j) {
                const int rn = wCol + j * 16 + (lane & 7) + ((lane >> 4) << 3);
                const int ku = s * 2 + ((lane >> 3) & 1);
                ldm_x4(bf[j], base + 16384u + (uint32_t)(rn * 8 + (ku ^ (rn & 7))) * 16);
            }
#pragma unroll
            for (int i = 0; i < 4; ++i)
#pragma unroll
                for (int j = 0; j < 4; ++j) {
                    mma16816(acc[i][j * 2 + 0], a[i], bf[j][0], bf[j][1]);
                    mma16816(acc[i][j * 2 + 1], a[i], bf[j][2], bf[j][3]);
                }
        }
    }
    // NOTE: no trailing sync needed inside loop; the sync at each iteration
    // start protects buffer reuse (load c+2 overwrites buffer of chunk c-1).

    // ---- direct epilogue ----
#pragma unroll
    for (int i = 0; i < 4; ++i) {
        const int row = rowBase + wRow + i * 16 + (lane >> 2);
#pragma unroll
        for (int j = 0; j < 8; ++j) {
            const int col = colBase + wCol + j * 8 + (lane & 3) * 2;
#pragma unroll
            for (int h = 0; h < 2; ++h) {
                const int rr = row + h * 8;
                if (rr < M) {
                    float v0 = acc[i][j][h * 2 + 0];
                    float v1 = acc[i][j][h * 2 + 1];
                    if (bias) {
                        if (col     < Nc) v0 += __ldg(bias + col);
                        if (col + 1 < Nc) v1 += __ldg(bias + col + 1);
                    }
                    if (relu) { v0 = fmaxf(v0, 0.f); v1 = fmaxf(v1, 0.f); }
                    if (col     < Nc) C[(size_t)rr * Nc + col]     = v0;
                    if (col + 1 < Nc) C[(size_t)rr * Nc + col + 1] = v1;
                }
            }
        }
    }

    // ---- symmetric mirror tile via smem transpose ----
    if (symm) {
        __syncthreads();                            // done reading smem tiles
        float* sc = (float*)smem;                   // [128][257]
#pragma unroll
        for (int i = 0; i < 4; ++i) {
            const int lr = wRow + i * 16 + (lane >> 2);
#pragma unroll
            for (int j = 0; j < 8; ++j) {
                const int lc = wCol + j * 8 + (lane & 3) * 2;
                sc[(lr    ) * 257 + lc    ] = acc[i][j][0];
                sc[(lr    ) * 257 + lc + 1] = acc[i][j][1];
                sc[(lr + 8) * 257 + lc    ] = acc[i][j][2];
                sc[(lr + 8) * 257 + lc + 1] = acc[i][j][3];
            }
        }
        __syncthreads();
        // mirror: D[colBase + rr][rowBase + 0..127] = sc[0..127][rr]
        for (int t = 0; t < 32; ++t) {
            const int rr = wid * 32 + t;
            float4 v;
            v.x = sc[(lane * 4 + 0) * 257 + rr];
            v.y = sc[(lane * 4 + 1) * 257 + rr];
            v.z = sc[(lane * 4 + 2) * 257 + rr];
            v.w = sc[(lane * 4 + 3) * 257 + rr];
            *(float4*)(C + (size_t)(colBase + rr) * Nc + rowBase + lane * 4) = v;
        }
    }
}

// ---------------- row L2 normalize (fp32 + bf16 copy) ------------------------
__global__ void normalize_kernel(const float* __restrict__ x) {
    int i = blockIdx.x;
    int tid = threadIdx.x;
    const float* xi = x + (size_t)i * DIM;
    float s = 0.f;
    for (int d = tid; d < DIM; d += 256) { float v = xi[d]; s += v * v; }
    __shared__ float sh[256];
    sh[tid] = s; __syncthreads();
    for (int o = 128; o > 0; o >>= 1) {
        if (tid < o) sh[tid] += sh[tid + o];
        __syncthreads();
    }
    float inv = 1.f / fmaxf(sqrtf(sh[0]), 1e-12f);
    float* out = g_xn + (size_t)i * DIM;
    __nv_bfloat16* outh = (__nv_bfloat16*)(g_xh) + (size_t)i * DIM;
    for (int d = tid; d < DIM; d += 256) {
        float v = xi[d] * inv;
        out[d] = v;
        outh[d] = __float2bfloat16(v);
    }
}

// ---------------- bf16 hi/lo split -------------------------------------------
__global__ void split_kernel(const float* __restrict__ src,
                             unsigned short* __restrict__ hi,
                             unsigned short* __restrict__ lo, size_t n) {
    size_t i = (size_t)blockIdx.x * 256 + threadIdx.x;
    if (i >= n) return;
    float v = src[i];
    __nv_bfloat16 h = __float2bfloat16(v);
    ((__nv_bfloat16*)hi)[i] = h;
    ((__nv_bfloat16*)lo)[i] = __float2bfloat16(v - __bfloat162float(h));
}

// ---------------- exact per-row top-16 candidates ----------------------------
__device__ __forceinline__ bool better(float v1, int i1, float v2, int i2) {
    return (v1 > v2) || (v1 == v2 && i1 < i2);
}

__global__ void topk_kernel() {
    int i = blockIdx.x;
    int tid = threadIdx.x;      // 128 threads
    const float* row = g_sim + (size_t)i * N_PTS;

    float bv[CAND]; int bi[CAND];
#pragma unroll
    for (int c = 0; c < CAND; ++c) { bv[c] = -INFINITY; bi[c] = 0x7fffffff; }

    for (int j = tid; j < N_PTS; j += 128) {
        float v = row[j];
        if (better(v, j, bv[CAND - 1], bi[CAND - 1])) {
            bv[CAND - 1] = v; bi[CAND - 1] = j;
#pragma unroll
            for (int c = CAND - 1; c > 0; --c) {
                if (better(bv[c], bi[c], bv[c - 1], bi[c - 1])) {
                    float tv = bv[c]; bv[c] = bv[c - 1]; bv[c - 1] = tv;
                    int   ti = bi[c]; bi[c] = bi[c - 1]; bi[c - 1] = ti;
                }
            }
        }
    }

    __shared__ float sv[128 * CAND];
    __shared__ int   si[128 * CAND];
    __shared__ float rv[128];
    __shared__ int   ri[128];
    __shared__ int   rp[128];
#pragma unroll
    for (int c = 0; c < CAND; ++c) { sv[tid * CAND + c] = bv[c]; si[tid * CAND + c] = bi[c]; }
    __syncthreads();

    for (int r = 0; r < CAND; ++r) {
        float best = -INFINITY; int besti = 0x7fffffff; int bestp = -1;
        for (int p = tid; p < 128 * CAND; p += 128) {
            if (better(sv[p], si[p], best, besti)) { best = sv[p]; besti = si[p]; bestp = p; }
        }
        rv[tid] = best; ri[tid] = besti; rp[tid] = bestp;
        __syncthreads();
        for (int o = 64; o > 0; o >>= 1) {
            if (tid < o) {
                if (better(rv[tid + o], ri[tid + o], rv[tid], ri[tid])) {
                    rv[tid] = rv[tid + o]; ri[tid] = ri[tid + o]; rp[tid] = rp[tid + o];
                }
            }
            __syncthreads();
        }
        if (tid == 0) {
            g_cand[(size_t)i * CAND + r] = ri[0];
            sv[rp[0]] = -INFINITY; si[rp[0]] = 0x7fffffff;
        }
        __syncthreads();
    }
}

// ---------------- exact fp32 rescore of 16 candidates -> top-6 ---------------
__global__ void rescore_kernel() {
    int i = blockIdx.x;
    int tid = threadIdx.x;      // 256
    int wid = tid >> 5, lane = tid & 31;
    __shared__ float xi[DIM];
    __shared__ int cand[CAND];
    __shared__ float red[CAND][8];
    for (int d = tid; d < DIM; d += 256) xi[d] = g_xn[(size_t)i * DIM + d];
    if (tid < CAND) cand[tid] = g_cand[(size_t)i * CAND + tid];
    __syncthreads();

    float acc[CAND];
#pragma unroll
    for (int c = 0; c < CAND; ++c) acc[c] = 0.f;
    for (int d = tid; d < DIM; d += 256) {
        float xv = xi[d];
#pragma unroll
        for (int c = 0; c < CAND; ++c)
            acc[c] += xv * g_xn[(size_t)cand[c] * DIM + d];
    }
#pragma unroll
    for (int c = 0; c < CAND; ++c) {
#pragma unroll
        for (int o = 16; o > 0; o >>= 1)
            acc[c] += __shfl_xor_sync(0xffffffffu, acc[c], o);
        if (lane == 0) red[c][wid] = acc[c];
    }
    __syncthreads();
    if (tid == 0) {
        float cv[CAND]; int ci[CAND];
#pragma unroll
        for (int c = 0; c < CAND; ++c) {
            float s = 0.f;
#pragma unroll
            for (int w = 0; w < 8; ++w) s += red[c][w];
            cv[c] = s; ci[c] = cand[c];
        }
        for (int r = 0; r < KNN; ++r) {
            int bp = r;
            for (int c = r + 1; c < CAND; ++c)
                if (better(cv[c], ci[c], cv[bp], ci[bp])) bp = c;
            float tv = cv[r]; cv[r] = cv[bp]; cv[bp] = tv;
            int   ti = ci[r]; ci[r] = ci[bp]; ci[bp] = ti;
            g_idx[(size_t)i * KNN + r] = ci[r];
        }
    }
}

// ---------------- k-reciprocal mask + GIN aggregation ------------------------
__global__ void aggr_kernel(const float* __restrict__ x) {
    int i = blockIdx.x;
    int tid = threadIdx.x;      // 256
    __shared__ int nb[KNN];
    __shared__ int ok[KNN];
    if (tid < KNN) {
        int j = g_idx[(size_t)i * KNN + tid];
        nb[tid] = j;
        int r = 0;
#pragma unroll
        for (int t = 0; t < KNN; ++t) r |= (g_idx[(size_t)j * KNN + t] == i);
        ok[tid] = r;
    }
    __syncthreads();
    for (int d = tid; d < DIM; d += 256) {
        float acc = GIN_ONE_PLUS_EPS * x[(size_t)i * DIM + d];
#pragma unroll
        for (int c = 0; c < KNN; ++c)
            if (ok[c]) acc += x[(size_t)nb[c] * DIM + d];
        g_h0[(size_t)i * DIM + d] = acc;
    }
}

// ---------------- BatchNorm (training-mode batch stats) ----------------------
__global__ void bn_zero_kernel() {
    int c = blockIdx.x * 256 + threadIdx.x;
    if (c < DIM) { g_scale[c] = 0.f; g_shift[c] = 0.f; }
}

__global__ void bn_stats_kernel() {
    int c  = blockIdx.x * 256 + threadIdx.x;
    int r0 = blockIdx.y * 256;
    float s = 0.f, q = 0.f;
    for (int r = r0; r < r0 + 256; ++r) {
        float v = g_h2[(size_t)r * DIM + c];
        s += v; q += v * v;
    }
    atomicAdd(&g_scale[c], s);
    atomicAdd(&g_shift[c], q);
}

__global__ void bn_finalize_kernel(const float* __restrict__ gamma,
                                   const float* __restrict__ beta) {
    int c = blockIdx.x * 256 + threadIdx.x;
    if (c >= DIM) return;
    const float invN = 1.f / (float)N_PTS;
    float mean = g_scale[c] * invN;
    float var  = g_shift[c] * invN - mean * mean;
    float sc   = gamma[c] * rsqrtf(var + BN_EPS);
    g_scale[c] = sc;
    g_shift[c] = beta[c] - mean * sc;
}

__global__ void bn_apply_kernel() {
    size_t idx = (size_t)blockIdx.x * 256 + threadIdx.x;
    int c = (int)(idx & (DIM - 1));
    g_hn[idx] = g_h2[idx] * g_scale[c] + g_shift[c];
}

// ---------------- launch -----------------------------------------------------
extern "C" void kernel_launch(void* const* d_in, const int* in_sizes, int n_in,
                              void* d_out, int out_size) {
    const float* x     = (const float*)d_in[0];
    const float* w1    = (const float*)d_in[1];
    const float* b1    = (const float*)d_in[2];
    const float* w2    = (const float*)d_in[3];
    const float* b2    = (const float*)d_in[4];
    const float* gamma = (const float*)d_in[5];
    const float* beta  = (const float*)d_in[6];
    const float* wc    = (const float*)d_in[7];
    float* out = (float*)d_out;

    cudaFuncSetAttribute(gemm_mma, cudaFuncAttributeMaxDynamicSharedMemorySize, SMEM_GEMM);

    float *p_xn, *p_sim, *p_h0, *p_h1, *p_h2, *p_hn;
    unsigned short *p_xh, *p_sh, *p_sl, *p_w1h, *p_w1l, *p_w2h, *p_w2l, *p_wch, *p_wcl;
    cudaGetSymbolAddress((void**)&p_xn,  g_xn);
    cudaGetSymbolAddress((void**)&p_sim, g_sim);
    cudaGetSymbolAddress((void**)&p_h0,  g_h0);
    cudaGetSymbolAddress((void**)&p_h1,  g_h1);
    cudaGetSymbolAddress((void**)&p_h2,  g_h2);
    cudaGetSymbolAddress((void**)&p_hn,  g_hn);
    cudaGetSymbolAddress((void**)&p_xh,  g_xh);
    cudaGetSymbolAddress((void**)&p_sh,  g_sh);
    cudaGetSymbolAddress((void**)&p_sl,  g_sl);
    cudaGetSymbolAddress((void**)&p_w1h, g_w1h);
    cudaGetSymbolAddress((void**)&p_w1l, g_w1l);
    cudaGetSymbolAddress((void**)&p_w2h, g_w2h);
    cudaGetSymbolAddress((void**)&p_w2l, g_w2l);
    cudaGetSymbolAddress((void**)&p_wch, g_wch);
    cudaGetSymbolAddress((void**)&p_wcl, g_wcl);

    const size_t nDD = (size_t)DIM * DIM;
    const size_t nCD = (size_t)NCLS * DIM;
    const size_t nND = (size_t)N_PTS * DIM;

    // 1) normalize (fp32 + bf16)
    normalize_kernel<<<N_PTS, 256>>>(x);

    // 2) weight splits
    split_kernel<<<(unsigned)((nDD + 255) / 256), 256>>>(w1, p_w1h, p_w1l, nDD);
    split_kernel<<<(unsigned)((nDD + 255) / 256), 256>>>(w2, p_w2h, p_w2l, nDD);
    split_kernel<<<(unsigned)((nCD + 255) / 256), 256>>>(wc, p_wch, p_wcl, nCD);

    // 3) similarity (bf16 HMMA, symmetric: compute 2bx<=by, mirror via smem)
    gemm_mma<<<dim3(32, 64), 256, SMEM_GEMM>>>(
        (const __nv_bfloat16*)p_xh, nullptr, (const __nv_bfloat16*)p_xh, nullptr,
        p_sim, N_PTS, N_PTS, DIM, nullptr, 0, 0, 1);

    // 4) top-16 candidates
    topk_kernel<<<N_PTS, 128>>>();

    // 5) exact fp32 rescore -> top-6
    rescore_kernel<<<N_PTS, 256>>>();

    // 6) k-reciprocal + GIN aggregation -> h0
    aggr_kernel<<<N_PTS, 256>>>(x);

    // 7) MLP layer 1 (bf16x3): relu(h0 @ w1^T + b1)
    split_kernel<<<(unsigned)(nND / 256), 256>>>(p_h0, p_sh, p_sl, nND);
    gemm_mma<<<dim3(8, 64), 256, SMEM_GEMM>>>(
        (const __nv_bfloat16*)p_sh, (const __nv_bfloat16*)p_sl,
        (const __nv_bfloat16*)p_w1h, (const __nv_bfloat16*)p_w1l,
        p_h1, N_PTS, DIM, DIM, b1, 1, 1, 0);

    // 8) MLP layer 2 (bf16x3)
    split_kernel<<<(unsigned)(nND / 256), 256>>>(p_h1, p_sh, p_sl, nND);
    gemm_mma<<<dim3(8, 64), 256, SMEM_GEMM>>>(
        (const __nv_bfloat16*)p_sh, (const __nv_bfloat16*)p_sl,
        (const __nv_bfloat16*)p_w2h, (const __nv_bfloat16*)p_w2l,
        p_h2, N_PTS, DIM, DIM, b2, 0, 1, 0);

    // 9) BatchNorm
    bn_zero_kernel<<<(DIM + 255) / 256, 256>>>();
    bn_stats_kernel<<<dim3(DIM / 256, N_PTS / 256), 256>>>();
    bn_finalize_kernel<<<(DIM + 255) / 256, 256>>>(gamma, beta);
    bn_apply_kernel<<<(unsigned)(nND / 256), 256>>>();

    // 10) classifier (bf16x3): hn @ wc^T -> out [8192, 751]
    split_kernel<<<(unsigned)(nND / 256), 256>>>(p_hn, p_sh, p_sl, nND);
    gemm_mma<<<dim3((NCLS + 255) / 256, 64), 256, SMEM_GEMM>>>(
        (const __nv_bfloat16*)p_sh, (const __nv_bfloat16*)p_sl,
        (const __nv_bfloat16*)p_wch, (const __nv_bfloat16*)p_wcl,
        out, N_PTS, NCLS, DIM, nullptr, 0, 1, 0);
}

// round 7
// speedup vs baseline: 1.1706x; 1.1706x over previous
#include <cuda_runtime.h>
#include <cuda_bf16.h>
#include <cstdint>
#include <math.h>

#define N_PTS 8192
#define DIM   2048
#define NCLS  751
#define KNN   6
#define CAND  16
#define GIN_ONE_PLUS_EPS 1.3f
#define BN_EPS 1e-5f

// ---------------- scratch ----------------------------------------------------
__device__ float g_xn [(size_t)N_PTS * DIM];
__device__ unsigned short g_xh [(size_t)N_PTS * DIM];     // bf16 of xn
__device__ float g_sim[(size_t)N_PTS * N_PTS];
__device__ int   g_cand[(size_t)N_PTS * CAND];
__device__ int   g_idx[(size_t)N_PTS * KNN];
__device__ float g_h2 [(size_t)N_PTS * DIM];
__device__ unsigned short g_sh [(size_t)N_PTS * DIM];     // act split hi (h0, later hn)
__device__ unsigned short g_sl [(size_t)N_PTS * DIM];     // act split lo
__device__ unsigned short g_th [(size_t)N_PTS * DIM];     // h1 split hi
__device__ unsigned short g_tl [(size_t)N_PTS * DIM];     // h1 split lo
__device__ unsigned short g_w1h[(size_t)DIM * DIM], g_w1l[(size_t)DIM * DIM];
__device__ unsigned short g_w2h[(size_t)DIM * DIM], g_w2l[(size_t)DIM * DIM];
__device__ unsigned short g_wch[(size_t)NCLS * DIM], g_wcl[(size_t)NCLS * DIM];
__device__ float g_scale[DIM];
__device__ float g_shift[DIM];

// ---------------- helpers ----------------------------------------------------
__device__ __forceinline__ uint32_t smem_to_u32(const void* p) {
    uint32_t a;
    asm("{ .reg .u64 t; cvta.to.shared.u64 t, %1; cvt.u32.u64 %0, t; }" : "=r"(a) : "l"(p));
    return a;
}

__device__ __forceinline__ void cp_async16(uint32_t dst, const void* src, int valid) {
    asm volatile("cp.async.cg.shared.global [%0], [%1], 16, %2;"
                 :: "r"(dst), "l"(src), "r"(valid ? 16 : 0) : "memory");
}
__device__ __forceinline__ void cp_commit() {
    asm volatile("cp.async.commit_group;" ::: "memory");
}
template <int N>
__device__ __forceinline__ void cp_wait() {
    asm volatile("cp.async.wait_group %0;" :: "n"(N) : "memory");
}

__device__ __forceinline__ void ldm_x4(uint32_t* r, uint32_t addr) {
    asm volatile("ldmatrix.sync.aligned.m8n8.x4.shared.b16 {%0,%1,%2,%3}, [%4];"
                 : "=r"(r[0]), "=r"(r[1]), "=r"(r[2]), "=r"(r[3]) : "r"(addr));
}

__device__ __forceinline__ void mma16816(float* d, const uint32_t* a, uint32_t b0, uint32_t b1) {
    asm volatile("mma.sync.aligned.m16n8k16.row.col.f32.bf16.bf16.f32 "
                 "{%0,%1,%2,%3}, {%4,%5,%6,%7}, {%8,%9}, {%0,%1,%2,%3};"
                 : "+f"(d[0]), "+f"(d[1]), "+f"(d[2]), "+f"(d[3])
                 : "r"(a[0]), "r"(a[1]), "r"(a[2]), "r"(a[3]), "r"(b0), "r"(b1));
}

__device__ __forceinline__ uint32_t pack_split_hi(float v0, float v1, uint32_t& lo_pack) {
    __nv_bfloat16 h0 = __float2bfloat16(v0);
    __nv_bfloat16 h1 = __float2bfloat16(v1);
    __nv_bfloat16 l0 = __float2bfloat16(v0 - __bfloat162float(h0));
    __nv_bfloat16 l1 = __float2bfloat16(v1 - __bfloat162float(h1));
    unsigned short uh0 = *(unsigned short*)&h0, uh1 = *(unsigned short*)&h1;
    unsigned short ul0 = *(unsigned short*)&l0, ul1 = *(unsigned short*)&l1;
    lo_pack = (uint32_t)ul0 | ((uint32_t)ul1 << 16);
    return (uint32_t)uh0 | ((uint32_t)uh1 << 16);
}

// ---------------- bf16 mma.sync GEMM: C[M,Nc] = A[M,K] * B[Nc,K]^T ----------
// 128x128 tile, BK=64, 256 thr (8 warps 4x2, warp tile 32x64), cp.async
// double buffer, XOR-swizzled smem, ldmatrix.x4 operands.
// three=1: acc = Ah*Bh + Ah*Bl + Al*Bh (hi/lo bf16 split, fp32 accum).
// symm=1 : only bx<=by tiles; mirror tile stored via smem transpose.
// omode : 0 -> fp32 to Cf;  1 -> bf16 hi/lo split pairs to Chi/Clo (Nc even).
#define SMEM_GEMM 66048   // max(2*32768 pipeline, 128*129*4 transpose stage)

__global__ __launch_bounds__(256, 2)
void gemm_mma(const __nv_bfloat16* __restrict__ Ah, const __nv_bfloat16* __restrict__ Al,
              const __nv_bfloat16* __restrict__ Bh, const __nv_bfloat16* __restrict__ Bl,
              float* __restrict__ Cf,
              unsigned short* __restrict__ Chi, unsigned short* __restrict__ Clo,
              int M, int Nc, int Kd,
              const float* __restrict__ bias, int relu, int three, int symm, int omode)
{
    const int bx = blockIdx.x, by = blockIdx.y;
    if (symm && bx > by) return;

    extern __shared__ char smem[];
    const uint32_t sb = smem_to_u32(smem);
    const int tid = threadIdx.x;
    const int lane = tid & 31;
    const int wid = tid >> 5;
    const int wm = wid & 3;          // 0..3  (M dir, 32 rows each)
    const int wn = wid >> 2;         // 0..1  (N dir, 64 cols each)
    const int wRow = wm * 32, wCol = wn * 64;

    const int rowBase = by * 128;
    const int colBase = bx * 128;
    const int kcount = Kd / 64;
    const int nchunk = (three ? 3 : 1) * kcount;

    float acc[2][8][4];
#pragma unroll
    for (int i = 0; i < 2; ++i)
#pragma unroll
        for (int j = 0; j < 8; ++j)
#pragma unroll
            for (int q = 0; q < 4; ++q) acc[i][j][q] = 0.f;

    auto load_chunk = [&](int c) {
        const int pass = three ? (c / kcount) : 0;
        const int k0 = (three ? (c % kcount) : c) * 64;
        const __nv_bfloat16* As = (pass == 2) ? Al : Ah;
        const __nv_bfloat16* Bs = (pass == 1) ? Bl : Bh;
        const uint32_t base = sb + (uint32_t)(c & 1) * 32768u;
#pragma unroll
        for (int i = 0; i < 4; ++i) {
            const int u = tid + i * 256;
            const int r = u >> 3, ku = u & 7;
            const int grow = rowBase + r;
            cp_async16(base + (uint32_t)(r * 8 + (ku ^ (r & 7))) * 16,
                       As + (size_t)grow * Kd + k0 + ku * 8, grow < M);
        }
#pragma unroll
        for (int i = 0; i < 4; ++i) {
            const int u = tid + i * 256;
            const int r = u >> 3, ku = u & 7;
            const int grow = colBase + r;
            cp_async16(base + 16384u + (uint32_t)(r * 8 + (ku ^ (r & 7))) * 16,
                       Bs + (size_t)grow * Kd + k0 + ku * 8, grow < Nc);
        }
        cp_commit();
    };

    load_chunk(0);

    for (int c = 0; c < nchunk; ++c) {
        if (c + 1 < nchunk) { load_chunk(c + 1); cp_wait<1>(); }
        else                { cp_wait<0>(); }
        __syncthreads();

        const uint32_t base = sb + (uint32_t)(c & 1) * 32768u;
#pragma unroll
        for (int s = 0; s < 4; ++s) {
            uint32_t a[2][4];
#pragma unroll
            for (int i = 0; i < 2; ++i) {
                const int r = wRow + i * 16 + (lane & 15);
                const int ku = s * 2 + (lane >> 4);
                ldm_x4(a[i], base + (uint32_t)(r * 8 + (ku ^ (r & 7))) * 16);
            }
            uint32_t bf[4][4];
#pragma unroll
            for (int j = 0; j < 4; ++j) {
                const int rn = wCol + j * 16 + (lane & 7) + ((lane >> 4) << 3);
                const int ku = s * 2 + ((lane >> 3) & 1);
                ldm_x4(bf[j], base + 16384u + (uint32_t)(rn * 8 + (ku ^ (rn & 7))) * 16);
            }
#pragma unroll
            for (int i = 0; i < 2; ++i)
#pragma unroll
                for (int j = 0; j < 4; ++j) {
                    mma16816(acc[i][j * 2 + 0], a[i], bf[j][0], bf[j][1]);
                    mma16816(acc[i][j * 2 + 1], a[i], bf[j][2], bf[j][3]);
                }
        }
        __syncthreads();
    }

    // ---- epilogue ----
    const int r0 = rowBase + wRow + (lane >> 2);
    const int lr0 = wRow + (lane >> 2);
#pragma unroll
    for (int i = 0; i < 2; ++i) {
#pragma unroll
        for (int j = 0; j < 8; ++j) {
            const int col = colBase + wCol + j * 8 + (lane & 3) * 2;
            const int row = r0 + i * 16;
#pragma unroll
            for (int h = 0; h < 2; ++h) {
                const int rr = row + h * 8;
                if (rr < M) {
                    float v0 = acc[i][j][h * 2 + 0];
                    float v1 = acc[i][j][h * 2 + 1];
                    if (bias) {
                        if (col     < Nc) v0 += __ldg(bias + col);
                        if (col + 1 < Nc) v1 += __ldg(bias + col + 1);
                    }
                    if (relu) { v0 = fmaxf(v0, 0.f); v1 = fmaxf(v1, 0.f); }
                    if (omode == 0) {
                        if (col     < Nc) Cf[(size_t)rr * Nc + col]     = v0;
                        if (col + 1 < Nc) Cf[(size_t)rr * Nc + col + 1] = v1;
                    } else if (col + 1 < Nc) {     // Nc even, aligned pair
                        uint32_t lo_pack;
                        uint32_t hi_pack = pack_split_hi(v0, v1, lo_pack);
                        *(uint32_t*)(Chi + (size_t)rr * Nc + col) = hi_pack;
                        *(uint32_t*)(Clo + (size_t)rr * Nc + col) = lo_pack;
                    }
                }
            }
        }
    }

    // ---- symmetric mirror tile via smem transpose ----
    if (symm && bx < by) {
        float* sc = (float*)smem;                  // [128][129]
#pragma unroll
        for (int i = 0; i < 2; ++i)
#pragma unroll
            for (int j = 0; j < 8; ++j) {
                const int lc = wCol + j * 8 + (lane & 3) * 2;
                const int lrr = lr0 + i * 16;
                sc[(lrr    ) * 129 + lc    ] = acc[i][j][0];
                sc[(lrr    ) * 129 + lc + 1] = acc[i][j][1];
                sc[(lrr + 8) * 129 + lc    ] = acc[i][j][2];
                sc[(lrr + 8) * 129 + lc + 1] = acc[i][j][3];
            }
        __syncthreads();
        const int tr = tid >> 1;                   // transposed-tile row 0..127
        const int half = (tid & 1) * 64;
        float* drow = Cf + (size_t)(colBase + tr) * Nc + rowBase + half;
#pragma unroll 8
        for (int i2 = 0; i2 < 64; ++i2)
            drow[i2] = sc[(half + i2) * 129 + tr];
    }
}

// ---------------- row L2 normalize (fp32 + bf16 copy) ------------------------
__global__ void normalize_kernel(const float* __restrict__ x) {
    int i = blockIdx.x;
    int tid = threadIdx.x;
    const float* xi = x + (size_t)i * DIM;
    float s = 0.f;
    for (int d = tid; d < DIM; d += 256) { float v = xi[d]; s += v * v; }
    __shared__ float sh[256];
    sh[tid] = s; __syncthreads();
    for (int o = 128; o > 0; o >>= 1) {
        if (tid < o) sh[tid] += sh[tid + o];
        __syncthreads();
    }
    float inv = 1.f / fmaxf(sqrtf(sh[0]), 1e-12f);
    float* out = g_xn + (size_t)i * DIM;
    __nv_bfloat16* outh = (__nv_bfloat16*)(g_xh) + (size_t)i * DIM;
    for (int d = tid; d < DIM; d += 256) {
        float v = xi[d] * inv;
        out[d] = v;
        outh[d] = __float2bfloat16(v);
    }
}

// ---------------- bf16 hi/lo split (weights only) ----------------------------
__global__ void split_kernel(const float* __restrict__ src,
                             unsigned short* __restrict__ hi,
                             unsigned short* __restrict__ lo, size_t n) {
    size_t i = (size_t)blockIdx.x * 256 + threadIdx.x;
    if (i >= n) return;
    float v = src[i];
    __nv_bfloat16 h = __float2bfloat16(v);
    ((__nv_bfloat16*)hi)[i] = h;
    ((__nv_bfloat16*)lo)[i] = __float2bfloat16(v - __bfloat162float(h));
}

// ---------------- exact per-row top-16 candidates ----------------------------
__device__ __forceinline__ bool better(float v1, int i1, float v2, int i2) {
    return (v1 > v2) || (v1 == v2 && i1 < i2);
}

__global__ void topk_kernel() {
    int i = blockIdx.x;
    int tid = threadIdx.x;      // 128 threads
    const float4* row = (const float4*)(g_sim + (size_t)i * N_PTS);

    float bv[CAND]; int bi[CAND];
#pragma unroll
    for (int c = 0; c < CAND; ++c) { bv[c] = -INFINITY; bi[c] = 0x7fffffff; }

    for (int j4 = tid; j4 < N_PTS / 4; j4 += 128) {
        float4 v4 = row[j4];
        float vv[4] = {v4.x, v4.y, v4.z, v4.w};
#pragma unroll
        for (int e = 0; e < 4; ++e) {
            const int j = j4 * 4 + e;
            const float v = vv[e];
            if (better(v, j, bv[CAND - 1], bi[CAND - 1])) {
                bv[CAND - 1] = v; bi[CAND - 1] = j;
#pragma unroll
                for (int c = CAND - 1; c > 0; --c) {
                    if (better(bv[c], bi[c], bv[c - 1], bi[c - 1])) {
                        float tv = bv[c]; bv[c] = bv[c - 1]; bv[c - 1] = tv;
                        int   ti = bi[c]; bi[c] = bi[c - 1]; bi[c - 1] = ti;
                    }
                }
            }
        }
    }

    __shared__ float sv[128 * CAND];
    __shared__ int   si[128 * CAND];
    __shared__ float rv[128];
    __shared__ int   ri[128];
    __shared__ int   rp[128];
#pragma unroll
    for (int c = 0; c < CAND; ++c) { sv[tid * CAND + c] = bv[c]; si[tid * CAND + c] = bi[c]; }
    __syncthreads();

    for (int r = 0; r < CAND; ++r) {
        float best = -INFINITY; int besti = 0x7fffffff; int bestp = -1;
        for (int p = tid; p < 128 * CAND; p += 128) {
            if (better(sv[p], si[p], best, besti)) { best = sv[p]; besti = si[p]; bestp = p; }
        }
        rv[tid] = best; ri[tid] = besti; rp[tid] = bestp;
        __syncthreads();
        for (int o = 64; o > 0; o >>= 1) {
            if (tid < o) {
                if (better(rv[tid + o], ri[tid + o], rv[tid], ri[tid])) {
                    rv[tid] = rv[tid + o]; ri[tid] = ri[tid + o]; rp[tid] = rp[tid + o];
                }
            }
            __syncthreads();
        }
        if (tid == 0) {
            g_cand[(size_t)i * CAND + r] = ri[0];
            sv[rp[0]] = -INFINITY; si[rp[0]] = 0x7fffffff;
        }
        __syncthreads();
    }
}

// ---------------- exact fp32 rescore of 16 candidates -> top-6 ---------------
__global__ void rescore_kernel() {
    int i = blockIdx.x;
    int tid = threadIdx.x;      // 256
    int wid = tid >> 5, lane = tid & 31;
    __shared__ float xi[DIM];
    __shared__ int cand[CAND];
    __shared__ float red[CAND][8];
    for (int d = tid; d < DIM; d += 256) xi[d] = g_xn[(size_t)i * DIM + d];
    if (tid < CAND) cand[tid] = g_cand[(size_t)i * CAND + tid];
    __syncthreads();

    float acc[CAND];
#pragma unroll
    for (int c = 0; c < CAND; ++c) acc[c] = 0.f;
    for (int d = tid; d < DIM; d += 256) {
        float xv = xi[d];
#pragma unroll
        for (int c = 0; c < CAND; ++c)
            acc[c] += xv * g_xn[(size_t)cand[c] * DIM + d];
    }
#pragma unroll
    for (int c = 0; c < CAND; ++c) {
#pragma unroll
        for (int o = 16; o > 0; o >>= 1)
            acc[c] += __shfl_xor_sync(0xffffffffu, acc[c], o);
        if (lane == 0) red[c][wid] = acc[c];
    }
    __syncthreads();
    if (tid == 0) {
        float cv[CAND]; int ci[CAND];
#pragma unroll
        for (int c = 0; c < CAND; ++c) {
            float s = 0.f;
#pragma unroll
            for (int w = 0; w < 8; ++w) s += red[c][w];
            cv[c] = s; ci[c] = cand[c];
        }
        for (int r = 0; r < KNN; ++r) {
            int bp = r;
            for (int c = r + 1; c < CAND; ++c)
                if (better(cv[c], ci[c], cv[bp], ci[bp])) bp = c;
            float tv = cv[r]; cv[r] = cv[bp]; cv[bp] = tv;
            int   ti = ci[r]; ci[r] = ci[bp]; ci[bp] = ti;
            g_idx[(size_t)i * KNN + r] = ci[r];
        }
    }
}

// ---------------- k-reciprocal + GIN aggregation -> h0 splits ----------------
__global__ void aggr_kernel(const float* __restrict__ x) {
    int i = blockIdx.x;
    int tid = threadIdx.x;      // 256
    __shared__ int nb[KNN];
    __shared__ int ok[KNN];
    if (tid < KNN) {
        int j = g_idx[(size_t)i * KNN + tid];
        nb[tid] = j;
        int r = 0;
#pragma unroll
        for (int t = 0; t < KNN; ++t) r |= (g_idx[(size_t)j * KNN + t] == i);
        ok[tid] = r;
    }
    __syncthreads();
    for (int d = tid; d < DIM; d += 256) {
        float acc = GIN_ONE_PLUS_EPS * x[(size_t)i * DIM + d];
#pragma unroll
        for (int c = 0; c < KNN; ++c)
            if (ok[c]) acc += x[(size_t)nb[c] * DIM + d];
        __nv_bfloat16 h = __float2bfloat16(acc);
        ((__nv_bfloat16*)g_sh)[(size_t)i * DIM + d] = h;
        ((__nv_bfloat16*)g_sl)[(size_t)i * DIM + d] =
            __float2bfloat16(acc - __bfloat162float(h));
    }
}

// ---------------- BatchNorm (training-mode batch stats) ----------------------
__global__ void bn_zero_kernel() {
    int c = blockIdx.x * 256 + threadIdx.x;
    if (c < DIM) { g_scale[c] = 0.f; g_shift[c] = 0.f; }
}

__global__ void bn_stats_kernel() {
    int c  = blockIdx.x * 256 + threadIdx.x;
    int r0 = blockIdx.y * 256;
    float s = 0.f, q = 0.f;
    for (int r = r0; r < r0 + 256; ++r) {
        float v = g_h2[(size_t)r * DIM + c];
        s += v; q += v * v;
    }
    atomicAdd(&g_scale[c], s);
    atomicAdd(&g_shift[c], q);
}

__global__ void bn_finalize_kernel(const float* __restrict__ gamma,
                                   const float* __restrict__ beta) {
    int c = blockIdx.x * 256 + threadIdx.x;
    if (c >= DIM) return;
    const float invN = 1.f / (float)N_PTS;
    float mean = g_scale[c] * invN;
    float var  = g_shift[c] * invN - mean * mean;
    float sc   = gamma[c] * rsqrtf(var + BN_EPS);
    g_scale[c] = sc;
    g_shift[c] = beta[c] - mean * sc;
}

// bn apply + hi/lo split fused
__global__ void bn_apply_kernel() {
    size_t idx = (size_t)blockIdx.x * 256 + threadIdx.x;
    int c = (int)(idx & (DIM - 1));
    float v = g_h2[idx] * g_scale[c] + g_shift[c];
    __nv_bfloat16 h = __float2bfloat16(v);
    ((__nv_bfloat16*)g_sh)[idx] = h;
    ((__nv_bfloat16*)g_sl)[idx] = __float2bfloat16(v - __bfloat162float(h));
}

// ---------------- launch -----------------------------------------------------
extern "C" void kernel_launch(void* const* d_in, const int* in_sizes, int n_in,
                              void* d_out, int out_size) {
    const float* x     = (const float*)d_in[0];
    const float* w1    = (const float*)d_in[1];
    const float* b1    = (const float*)d_in[2];
    const float* w2    = (const float*)d_in[3];
    const float* b2    = (const float*)d_in[4];
    const float* gamma = (const float*)d_in[5];
    const float* beta  = (const float*)d_in[6];
    const float* wc    = (const float*)d_in[7];
    float* out = (float*)d_out;

    cudaFuncSetAttribute(gemm_mma, cudaFuncAttributeMaxDynamicSharedMemorySize, SMEM_GEMM);

    float *p_xn, *p_sim, *p_h2;
    unsigned short *p_xh, *p_sh, *p_sl, *p_th, *p_tl;
    unsigned short *p_w1h, *p_w1l, *p_w2h, *p_w2l, *p_wch, *p_wcl;
    cudaGetSymbolAddress((void**)&p_xn,  g_xn);
    cudaGetSymbolAddress((void**)&p_sim, g_sim);
    cudaGetSymbolAddress((void**)&p_h2,  g_h2);
    cudaGetSymbolAddress((void**)&p_xh,  g_xh);
    cudaGetSymbolAddress((void**)&p_sh,  g_sh);
    cudaGetSymbolAddress((void**)&p_sl,  g_sl);
    cudaGetSymbolAddress((void**)&p_th,  g_th);
    cudaGetSymbolAddress((void**)&p_tl,  g_tl);
    cudaGetSymbolAddress((void**)&p_w1h, g_w1h);
    cudaGetSymbolAddress((void**)&p_w1l, g_w1l);
    cudaGetSymbolAddress((void**)&p_w2h, g_w2h);
    cudaGetSymbolAddress((void**)&p_w2l, g_w2l);
    cudaGetSymbolAddress((void**)&p_wch, g_wch);
    cudaGetSymbolAddress((void**)&p_wcl, g_wcl);

    const size_t nDD = (size_t)DIM * DIM;
    const size_t nCD = (size_t)NCLS * DIM;
    const size_t nND = (size_t)N_PTS * DIM;

    // 1) normalize (fp32 + bf16)
    normalize_kernel<<<N_PTS, 256>>>(x);

    // 2) weight splits
    split_kernel<<<(unsigned)((nDD + 255) / 256), 256>>>(w1, p_w1h, p_w1l, nDD);
    split_kernel<<<(unsigned)((nDD + 255) / 256), 256>>>(w2, p_w2h, p_w2l, nDD);
    split_kernel<<<(unsigned)((nCD + 255) / 256), 256>>>(wc, p_wch, p_wcl, nCD);

    // 3) similarity (bf16 HMMA, symmetric: compute bx<=by, mirror via smem)
    gemm_mma<<<dim3(64, 64), 256, SMEM_GEMM>>>(
        (const __nv_bfloat16*)p_xh, nullptr, (const __nv_bfloat16*)p_xh, nullptr,
        p_sim, nullptr, nullptr, N_PTS, N_PTS, DIM, nullptr, 0, 0, 1, 0);

    // 4) top-16 candidates
    topk_kernel<<<N_PTS, 128>>>();

    // 5) exact fp32 rescore -> top-6
    rescore_kernel<<<N_PTS, 256>>>();

    // 6) k-reciprocal + GIN aggregation -> h0 splits (g_sh/g_sl)
    aggr_kernel<<<N_PTS, 256>>>(x);

    // 7) MLP layer 1 (bf16x3): relu(h0 @ w1^T + b1) -> h1 splits (g_th/g_tl)
    gemm_mma<<<dim3(16, 64), 256, SMEM_GEMM>>>(
        (const __nv_bfloat16*)p_sh, (const __nv_bfloat16*)p_sl,
        (const __nv_bfloat16*)p_w1h, (const __nv_bfloat16*)p_w1l,
        nullptr, p_th, p_tl, N_PTS, DIM, DIM, b1, 1, 1, 0, 1);

    // 8) MLP layer 2 (bf16x3): h1 @ w2^T + b2 -> h2 fp32
    gemm_mma<<<dim3(16, 64), 256, SMEM_GEMM>>>(
        (const __nv_bfloat16*)p_th, (const __nv_bfloat16*)p_tl,
        (const __nv_bfloat16*)p_w2h, (const __nv_bfloat16*)p_w2l,
        p_h2, nullptr, nullptr, N_PTS, DIM, DIM, b2, 0, 1, 0, 0);

    // 9) BatchNorm -> hn splits (g_sh/g_sl)
    bn_zero_kernel<<<(DIM + 255) / 256, 256>>>();
    bn_stats_kernel<<<dim3(DIM / 256, N_PTS / 256), 256>>>();
    bn_finalize_kernel<<<(DIM + 255) / 256, 256>>>(gamma, beta);
    bn_apply_kernel<<<(unsigned)(nND / 256), 256>>>();

    // 10) classifier (bf16x3): hn @ wc^T -> out [8192, 751]
    gemm_mma<<<dim3((NCLS + 127) / 128, 64), 256, SMEM_GEMM>>>(
        (const __nv_bfloat16*)p_sh, (const __nv_bfloat16*)p_sl,
        (const __nv_bfloat16*)p_wch, (const __nv_bfloat16*)p_wcl,
        out, nullptr, nullptr, N_PTS, NCLS, DIM, nullptr, 0, 1, 0, 0);
}

// round 8
// speedup vs baseline: 1.1902x; 1.0167x over previous
#include <cuda_runtime.h>
#include <cuda_bf16.h>
#include <cstdint>
#include <math.h>

#define N_PTS 8192
#define DIM   2048
#define NCLS  751
#define KNN   6
#define CAND  16
#define GIN_ONE_PLUS_EPS 1.3f
#define BN_EPS 1e-5f

// ---------------- scratch ----------------------------------------------------
__device__ float g_xn [(size_t)N_PTS * DIM];
__device__ unsigned short g_xh [(size_t)N_PTS * DIM];     // bf16 of xn
__device__ float g_sim[(size_t)N_PTS * N_PTS];
__device__ int   g_cand[(size_t)N_PTS * CAND];
__device__ int   g_idx[(size_t)N_PTS * KNN];
__device__ float g_h2 [(size_t)N_PTS * DIM];
__device__ unsigned short g_sh [(size_t)N_PTS * DIM];     // act split hi (h0, later hn)
__device__ unsigned short g_sl [(size_t)N_PTS * DIM];     // act split lo
__device__ unsigned short g_th [(size_t)N_PTS * DIM];     // h1 split hi
__device__ unsigned short g_tl [(size_t)N_PTS * DIM];     // h1 split lo
__device__ unsigned short g_w1h[(size_t)DIM * DIM], g_w1l[(size_t)DIM * DIM];
__device__ unsigned short g_w2h[(size_t)DIM * DIM], g_w2l[(size_t)DIM * DIM];
__device__ unsigned short g_wch[(size_t)NCLS * DIM], g_wcl[(size_t)NCLS * DIM];
__device__ float g_scale[DIM];
__device__ float g_shift[DIM];

// ---------------- helpers ----------------------------------------------------
__device__ __forceinline__ uint32_t smem_to_u32(const void* p) {
    uint32_t a;
    asm("{ .reg .u64 t; cvta.to.shared.u64 t, %1; cvt.u32.u64 %0, t; }" : "=r"(a) : "l"(p));
    return a;
}

__device__ __forceinline__ void cp_async16(uint32_t dst, const void* src, int valid) {
    asm volatile("cp.async.cg.shared.global [%0], [%1], 16, %2;"
                 :: "r"(dst), "l"(src), "r"(valid ? 16 : 0) : "memory");
}
__device__ __forceinline__ void cp_commit() {
    asm volatile("cp.async.commit_group;" ::: "memory");
}
template <int N>
__device__ __forceinline__ void cp_wait() {
    asm volatile("cp.async.wait_group %0;" :: "n"(N) : "memory");
}

__device__ __forceinline__ void ldm_x4(uint32_t* r, uint32_t addr) {
    asm volatile("ldmatrix.sync.aligned.m8n8.x4.shared.b16 {%0,%1,%2,%3}, [%4];"
                 : "=r"(r[0]), "=r"(r[1]), "=r"(r[2]), "=r"(r[3]) : "r"(addr));
}

__device__ __forceinline__ void mma16816(float* d, const uint32_t* a, uint32_t b0, uint32_t b1) {
    asm volatile("mma.sync.aligned.m16n8k16.row.col.f32.bf16.bf16.f32 "
                 "{%0,%1,%2,%3}, {%4,%5,%6,%7}, {%8,%9}, {%0,%1,%2,%3};"
                 : "+f"(d[0]), "+f"(d[1]), "+f"(d[2]), "+f"(d[3])
                 : "r"(a[0]), "r"(a[1]), "r"(a[2]), "r"(a[3]), "r"(b0), "r"(b1));
}

__device__ __forceinline__ uint32_t pack_split_hi(float v0, float v1, uint32_t& lo_pack) {
    __nv_bfloat16 h0 = __float2bfloat16(v0);
    __nv_bfloat16 h1 = __float2bfloat16(v1);
    __nv_bfloat16 l0 = __float2bfloat16(v0 - __bfloat162float(h0));
    __nv_bfloat16 l1 = __float2bfloat16(v1 - __bfloat162float(h1));
    unsigned short uh0 = *(unsigned short*)&h0, uh1 = *(unsigned short*)&h1;
    unsigned short ul0 = *(unsigned short*)&l0, ul1 = *(unsigned short*)&l1;
    lo_pack = (uint32_t)ul0 | ((uint32_t)ul1 << 16);
    return (uint32_t)uh0 | ((uint32_t)uh1 << 16);
}

// ---------------- bf16 mma.sync GEMM: C[M,Nc] = A[M,K] * B[Nc,K]^T ----------
// 128x128 CTA tile, BK=64, 128 thr (4 warps 2x2, warp tile 64x64), cp.async
// double buffer, XOR-swizzled smem, ldmatrix.x4 operands, 2 CTAs/SM.
// three=1: acc = Ah*Bh + Ah*Bl + Al*Bh (hi/lo bf16 split, fp32 accum).
// symm=1 : only bx<=by tiles; mirror tile stored via smem transpose.
// omode : 0 -> fp32 to Cf;  1 -> bf16 hi/lo split pairs to Chi/Clo (Nc even).
#define SMEM_GEMM 66048   // max(2*32768 pipeline, 128*129*4 transpose stage)

__global__ __launch_bounds__(128, 2)
void gemm_mma(const __nv_bfloat16* __restrict__ Ah, const __nv_bfloat16* __restrict__ Al,
              const __nv_bfloat16* __restrict__ Bh, const __nv_bfloat16* __restrict__ Bl,
              float* __restrict__ Cf,
              unsigned short* __restrict__ Chi, unsigned short* __restrict__ Clo,
              int M, int Nc, int Kd,
              const float* __restrict__ bias, int relu, int three, int symm, int omode)
{
    const int bx = blockIdx.x, by = blockIdx.y;
    if (symm && bx > by) return;

    extern __shared__ char smem[];
    const uint32_t sb = smem_to_u32(smem);
    const int tid = threadIdx.x;
    const int lane = tid & 31;
    const int wid = tid >> 5;        // 0..3
    const int wm = wid & 1;          // M dir (64 rows each)
    const int wn = wid >> 1;         // N dir (64 cols each)
    const int wRow = wm * 64, wCol = wn * 64;

    const int rowBase = by * 128;
    const int colBase = bx * 128;
    const int kcount = Kd / 64;
    const int nchunk = (three ? 3 : 1) * kcount;

    float acc[4][8][4];
#pragma unroll
    for (int i = 0; i < 4; ++i)
#pragma unroll
        for (int j = 0; j < 8; ++j)
#pragma unroll
            for (int q = 0; q < 4; ++q) acc[i][j][q] = 0.f;

    auto load_chunk = [&](int c) {
        const int pass = three ? (c / kcount) : 0;
        const int k0 = (three ? (c % kcount) : c) * 64;
        const __nv_bfloat16* As = (pass == 2) ? Al : Ah;
        const __nv_bfloat16* Bs = (pass == 1) ? Bl : Bh;
        const uint32_t base = sb + (uint32_t)(c & 1) * 32768u;
#pragma unroll
        for (int i = 0; i < 8; ++i) {              // A tile: 1024 x 16B
            const int u = tid + i * 128;
            const int r = u >> 3, ku = u & 7;
            const int grow = rowBase + r;
            cp_async16(base + (uint32_t)(r * 8 + (ku ^ (r & 7))) * 16,
                       As + (size_t)grow * Kd + k0 + ku * 8, grow < M);
        }
#pragma unroll
        for (int i = 0; i < 8; ++i) {              // B tile: 1024 x 16B
            const int u = tid + i * 128;
            const int r = u >> 3, ku = u & 7;
            const int grow = colBase + r;
            cp_async16(base + 16384u + (uint32_t)(r * 8 + (ku ^ (r & 7))) * 16,
                       Bs + (size_t)grow * Kd + k0 + ku * 8, grow < Nc);
        }
        cp_commit();
    };

    load_chunk(0);

    for (int c = 0; c < nchunk; ++c) {
        if (c + 1 < nchunk) { load_chunk(c + 1); cp_wait<1>(); }
        else                { cp_wait<0>(); }
        __syncthreads();

        const uint32_t base = sb + (uint32_t)(c & 1) * 32768u;
#pragma unroll
        for (int s = 0; s < 4; ++s) {              // four k16 steps
            uint32_t a[4][4];
#pragma unroll
            for (int i = 0; i < 4; ++i) {
                const int r = wRow + i * 16 + (lane & 15);
                const int ku = s * 2 + (lane >> 4);
                ldm_x4(a[i], base + (uint32_t)(r * 8 + (ku ^ (r & 7))) * 16);
            }
            uint32_t bf[4][4];
#pragma unroll
            for (int j = 0; j < 4; ++j) {
                const int rn = wCol + j * 16 + (lane & 7) + ((lane >> 4) << 3);
                const int ku = s * 2 + ((lane >> 3) & 1);
                ldm_x4(bf[j], base + 16384u + (uint32_t)(rn * 8 + (ku ^ (rn & 7))) * 16);
            }
#pragma unroll
            for (int i = 0; i < 4; ++i)
#pragma unroll
                for (int j = 0; j < 4; ++j) {
                    mma16816(acc[i][j * 2 + 0], a[i], bf[j][0], bf[j][1]);
                    mma16816(acc[i][j * 2 + 1], a[i], bf[j][2], bf[j][3]);
                }
        }
        __syncthreads();
    }

    // ---- epilogue ----
#pragma unroll
    for (int i = 0; i < 4; ++i) {
        const int row = rowBase + wRow + i * 16 + (lane >> 2);
#pragma unroll
        for (int j = 0; j < 8; ++j) {
            const int col = colBase + wCol + j * 8 + (lane & 3) * 2;
#pragma unroll
            for (int h = 0; h < 2; ++h) {
                const int rr = row + h * 8;
                if (rr < M) {
                    float v0 = acc[i][j][h * 2 + 0];
                    float v1 = acc[i][j][h * 2 + 1];
                    if (bias) {
                        if (col     < Nc) v0 += __ldg(bias + col);
                        if (col + 1 < Nc) v1 += __ldg(bias + col + 1);
                    }
                    if (relu) { v0 = fmaxf(v0, 0.f); v1 = fmaxf(v1, 0.f); }
                    if (omode == 0) {
                        if (col     < Nc) Cf[(size_t)rr * Nc + col]     = v0;
                        if (col + 1 < Nc) Cf[(size_t)rr * Nc + col + 1] = v1;
                    } else if (col + 1 < Nc) {     // Nc even, aligned pair
                        uint32_t lo_pack;
                        uint32_t hi_pack = pack_split_hi(v0, v1, lo_pack);
                        *(uint32_t*)(Chi + (size_t)rr * Nc + col) = hi_pack;
                        *(uint32_t*)(Clo + (size_t)rr * Nc + col) = lo_pack;
                    }
                }
            }
        }
    }

    // ---- symmetric mirror tile via smem transpose (coalesced writes) ----
    if (symm && bx < by) {
        float* sc = (float*)smem;                  // [128][129]
#pragma unroll
        for (int i = 0; i < 4; ++i) {
            const int lr = wRow + i * 16 + (lane >> 2);
#pragma unroll
            for (int j = 0; j < 8; ++j) {
                const int lc = wCol + j * 8 + (lane & 3) * 2;
                sc[(lr    ) * 129 + lc    ] = acc[i][j][0];
                sc[(lr    ) * 129 + lc + 1] = acc[i][j][1];
                sc[(lr + 8) * 129 + lc    ] = acc[i][j][2];
                sc[(lr + 8) * 129 + lc + 1] = acc[i][j][3];
            }
        }
        __syncthreads();
        // D[colBase+cc][rowBase+tid] = sc[tid][cc]; writes coalesced per cc
        for (int cc = 0; cc < 128; ++cc)
            Cf[(size_t)(colBase + cc) * Nc + rowBase + tid] = sc[tid * 129 + cc];
    }
}

// ---------------- row L2 normalize (fp32 + bf16 copy) ------------------------
__global__ void normalize_kernel(const float* __restrict__ x) {
    int i = blockIdx.x;
    int tid = threadIdx.x;
    const float* xi = x + (size_t)i * DIM;
    float s = 0.f;
    for (int d = tid; d < DIM; d += 256) { float v = xi[d]; s += v * v; }
    __shared__ float sh[256];
    sh[tid] = s; __syncthreads();
    for (int o = 128; o > 0; o >>= 1) {
        if (tid < o) sh[tid] += sh[tid + o];
        __syncthreads();
    }
    float inv = 1.f / fmaxf(sqrtf(sh[0]), 1e-12f);
    float* out = g_xn + (size_t)i * DIM;
    __nv_bfloat16* outh = (__nv_bfloat16*)(g_xh) + (size_t)i * DIM;
    for (int d = tid; d < DIM; d += 256) {
        float v = xi[d] * inv;
        out[d] = v;
        outh[d] = __float2bfloat16(v);
    }
}

// ---------------- bf16 hi/lo split (weights only) ----------------------------
__global__ void split_kernel(const float* __restrict__ src,
                             unsigned short* __restrict__ hi,
                             unsigned short* __restrict__ lo, size_t n) {
    size_t i = (size_t)blockIdx.x * 256 + threadIdx.x;
    if (i >= n) return;
    float v = src[i];
    __nv_bfloat16 h = __float2bfloat16(v);
    ((__nv_bfloat16*)hi)[i] = h;
    ((__nv_bfloat16*)lo)[i] = __float2bfloat16(v - __bfloat162float(h));
}

// ---------------- exact per-row top-16 candidates ----------------------------
__device__ __forceinline__ bool better(float v1, int i1, float v2, int i2) {
    return (v1 > v2) || (v1 == v2 && i1 < i2);
}

__global__ void topk_kernel() {
    int i = blockIdx.x;
    int tid = threadIdx.x;      // 128 threads
    const float4* row = (const float4*)(g_sim + (size_t)i * N_PTS);

    float bv[CAND]; int bi[CAND];
#pragma unroll
    for (int c = 0; c < CAND; ++c) { bv[c] = -INFINITY; bi[c] = 0x7fffffff; }

    for (int j4 = tid; j4 < N_PTS / 4; j4 += 128) {
        float4 v4 = row[j4];
        float vv[4] = {v4.x, v4.y, v4.z, v4.w};
#pragma unroll
        for (int e = 0; e < 4; ++e) {
            const int j = j4 * 4 + e;
            const float v = vv[e];
            if (better(v, j, bv[CAND - 1], bi[CAND - 1])) {
                bv[CAND - 1] = v; bi[CAND - 1] = j;
#pragma unroll
                for (int c = CAND - 1; c > 0; --c) {
                    if (better(bv[c], bi[c], bv[c - 1], bi[c - 1])) {
                        float tv = bv[c]; bv[c] = bv[c - 1]; bv[c - 1] = tv;
                        int   ti = bi[c]; bi[c] = bi[c - 1]; bi[c - 1] = ti;
                    }
                }
            }
        }
    }

    __shared__ float sv[128 * CAND];
    __shared__ int   si[128 * CAND];
    __shared__ float rv[128];
    __shared__ int   ri[128];
    __shared__ int   rp[128];
#pragma unroll
    for (int c = 0; c < CAND; ++c) { sv[tid * CAND + c] = bv[c]; si[tid * CAND + c] = bi[c]; }
    __syncthreads();

    for (int r = 0; r < CAND; ++r) {
        float best = -INFINITY; int besti = 0x7fffffff; int bestp = -1;
        for (int p = tid; p < 128 * CAND; p += 128) {
            if (better(sv[p], si[p], best, besti)) { best = sv[p]; besti = si[p]; bestp = p; }
        }
        rv[tid] = best; ri[tid] = besti; rp[tid] = bestp;
        __syncthreads();
        for (int o = 64; o > 0; o >>= 1) {
            if (tid < o) {
                if (better(rv[tid + o], ri[tid + o], rv[tid], ri[tid])) {
                    rv[tid] = rv[tid + o]; ri[tid] = ri[tid + o]; rp[tid] = rp[tid + o];
                }
            }
            __syncthreads();
        }
        if (tid == 0) {
            g_cand[(size_t)i * CAND + r] = ri[0];
            sv[rp[0]] = -INFINITY; si[rp[0]] = 0x7fffffff;
        }
        __syncthreads();
    }
}

// ---------------- exact fp32 rescore of 16 candidates -> top-6 ---------------
__global__ void rescore_kernel() {
    int i = blockIdx.x;
    int tid = threadIdx.x;      // 256
    int wid = tid >> 5, lane = tid & 31;
    __shared__ float xi[DIM];
    __shared__ int cand[CAND];
    __shared__ float red[CAND][8];
    for (int d = tid; d < DIM; d += 256) xi[d] = g_xn[(size_t)i * DIM + d];
    if (tid < CAND) cand[tid] = g_cand[(size_t)i * CAND + tid];
    __syncthreads();

    float acc[CAND];
#pragma unroll
    for (int c = 0; c < CAND; ++c) acc[c] = 0.f;
    for (int d = tid; d < DIM; d += 256) {
        float xv = xi[d];
#pragma unroll
        for (int c = 0; c < CAND; ++c)
            acc[c] += xv * g_xn[(size_t)cand[c] * DIM + d];
    }
#pragma unroll
    for (int c = 0; c < CAND; ++c) {
#pragma unroll
        for (int o = 16; o > 0; o >>= 1)
            acc[c] += __shfl_xor_sync(0xffffffffu, acc[c], o);
        if (lane == 0) red[c][wid] = acc[c];
    }
    __syncthreads();
    if (tid == 0) {
        float cv[CAND]; int ci[CAND];
#pragma unroll
        for (int c = 0; c < CAND; ++c) {
            float s = 0.f;
#pragma unroll
            for (int w = 0; w < 8; ++w) s += red[c][w];
            cv[c] = s; ci[c] = cand[c];
        }
        for (int r = 0; r < KNN; ++r) {
            int bp = r;
            for (int c = r + 1; c < CAND; ++c)
                if (better(cv[c], ci[c], cv[bp], ci[bp])) bp = c;
            float tv = cv[r]; cv[r] = cv[bp]; cv[bp] = tv;
            int   ti = ci[r]; ci[r] = ci[bp]; ci[bp] = ti;
            g_idx[(size_t)i * KNN + r] = ci[r];
        }
    }
}

// ---------------- k-reciprocal + GIN aggregation -> h0 splits ----------------
__global__ void aggr_kernel(const float* __restrict__ x) {
    int i = blockIdx.x;
    int tid = threadIdx.x;      // 256
    __shared__ int nb[KNN];
    __shared__ int ok[KNN];
    if (tid < KNN) {
        int j = g_idx[(size_t)i * KNN + tid];
        nb[tid] = j;
        int r = 0;
#pragma unroll
        for (int t = 0; t < KNN; ++t) r |= (g_idx[(size_t)j * KNN + t] == i);
        ok[tid] = r;
    }
    __syncthreads();
    for (int d = tid; d < DIM; d += 256) {
        float acc = GIN_ONE_PLUS_EPS * x[(size_t)i * DIM + d];
#pragma unroll
        for (int c = 0; c < KNN; ++c)
            if (ok[c]) acc += x[(size_t)nb[c] * DIM + d];
        __nv_bfloat16 h = __float2bfloat16(acc);
        ((__nv_bfloat16*)g_sh)[(size_t)i * DIM + d] = h;
        ((__nv_bfloat16*)g_sl)[(size_t)i * DIM + d] =
            __float2bfloat16(acc - __bfloat162float(h));
    }
}

// ---------------- BatchNorm (training-mode batch stats) ----------------------
__global__ void bn_zero_kernel() {
    int c = blockIdx.x * 256 + threadIdx.x;
    if (c < DIM) { g_scale[c] = 0.f; g_shift[c] = 0.f; }
}

__global__ void bn_stats_kernel() {
    int c  = blockIdx.x * 256 + threadIdx.x;
    int r0 = blockIdx.y * 256;
    float s = 0.f, q = 0.f;
    for (int r = r0; r < r0 + 256; ++r) {
        float v = g_h2[(size_t)r * DIM + c];
        s += v; q += v * v;
    }
    atomicAdd(&g_scale[c], s);
    atomicAdd(&g_shift[c], q);
}

__global__ void bn_finalize_kernel(const float* __restrict__ gamma,
                                   const float* __restrict__ beta) {
    int c = blockIdx.x * 256 + threadIdx.x;
    if (c >= DIM) return;
    const float invN = 1.f / (float)N_PTS;
    float mean = g_scale[c] * invN;
    float var  = g_shift[c] * invN - mean * mean;
    float sc   = gamma[c] * rsqrtf(var + BN_EPS);
    g_scale[c] = sc;
    g_shift[c] = beta[c] - mean * sc;
}

// bn apply + hi/lo split fused
__global__ void bn_apply_kernel() {
    size_t idx = (size_t)blockIdx.x * 256 + threadIdx.x;
    int c = (int)(idx & (DIM - 1));
    float v = g_h2[idx] * g_scale[c] + g_shift[c];
    __nv_bfloat16 h = __float2bfloat16(v);
    ((__nv_bfloat16*)g_sh)[idx] = h;
    ((__nv_bfloat16*)g_sl)[idx] = __float2bfloat16(v - __bfloat162float(h));
}

// ---------------- launch -----------------------------------------------------
extern "C" void kernel_launch(void* const* d_in, const int* in_sizes, int n_in,
                              void* d_out, int out_size) {
    const float* x     = (const float*)d_in[0];
    const float* w1    = (const float*)d_in[1];
    const float* b1    = (const float*)d_in[2];
    const float* w2    = (const float*)d_in[3];
    const float* b2    = (const float*)d_in[4];
    const float* gamma = (const float*)d_in[5];
    const float* beta  = (const float*)d_in[6];
    const float* wc    = (const float*)d_in[7];
    float* out = (float*)d_out;

    cudaFuncSetAttribute(gemm_mma, cudaFuncAttributeMaxDynamicSharedMemorySize, SMEM_GEMM);

    float *p_xn, *p_sim, *p_h2;
    unsigned short *p_xh, *p_sh, *p_sl, *p_th, *p_tl;
    unsigned short *p_w1h, *p_w1l, *p_w2h, *p_w2l, *p_wch, *p_wcl;
    cudaGetSymbolAddress((void**)&p_xn,  g_xn);
    cudaGetSymbolAddress((void**)&p_sim, g_sim);
    cudaGetSymbolAddress((void**)&p_h2,  g_h2);
    cudaGetSymbolAddress((void**)&p_xh,  g_xh);
    cudaGetSymbolAddress((void**)&p_sh,  g_sh);
    cudaGetSymbolAddress((void**)&p_sl,  g_sl);
    cudaGetSymbolAddress((void**)&p_th,  g_th);
    cudaGetSymbolAddress((void**)&p_tl,  g_tl);
    cudaGetSymbolAddress((void**)&p_w1h, g_w1h);
    cudaGetSymbolAddress((void**)&p_w1l, g_w1l);
    cudaGetSymbolAddress((void**)&p_w2h, g_w2h);
    cudaGetSymbolAddress((void**)&p_w2l, g_w2l);
    cudaGetSymbolAddress((void**)&p_wch, g_wch);
    cudaGetSymbolAddress((void**)&p_wcl, g_wcl);

    const size_t nDD = (size_t)DIM * DIM;
    const size_t nCD = (size_t)NCLS * DIM;
    const size_t nND = (size_t)N_PTS * DIM;

    // 1) normalize (fp32 + bf16)
    normalize_kernel<<<N_PTS, 256>>>(x);

    // 2) weight splits
    split_kernel<<<(unsigned)((nDD + 255) / 256), 256>>>(w1, p_w1h, p_w1l, nDD);
    split_kernel<<<(unsigned)((nDD + 255) / 256), 256>>>(w2, p_w2h, p_w2l, nDD);
    split_kernel<<<(unsigned)((nCD + 255) / 256), 256>>>(wc, p_wch, p_wcl, nCD);

    // 3) similarity (bf16 HMMA, symmetric: compute bx<=by, mirror via smem)
    gemm_mma<<<dim3(64, 64), 128, SMEM_GEMM>>>(
        (const __nv_bfloat16*)p_xh, nullptr, (const __nv_bfloat16*)p_xh, nullptr,
        p_sim, nullptr, nullptr, N_PTS, N_PTS, DIM, nullptr, 0, 0, 1, 0);

    // 4) top-16 candidates
    topk_kernel<<<N_PTS, 128>>>();

    // 5) exact fp32 rescore -> top-6
    rescore_kernel<<<N_PTS, 256>>>();

    // 6) k-reciprocal + GIN aggregation -> h0 splits (g_sh/g_sl)
    aggr_kernel<<<N_PTS, 256>>>(x);

    // 7) MLP layer 1 (bf16x3): relu(h0 @ w1^T + b1) -> h1 splits (g_th/g_tl)
    gemm_mma<<<dim3(16, 64), 128, SMEM_GEMM>>>(
        (const __nv_bfloat16*)p_sh, (const __nv_bfloat16*)p_sl,
        (const __nv_bfloat16*)p_w1h, (const __nv_bfloat16*)p_w1l,
        nullptr, p_th, p_tl, N_PTS, DIM, DIM, b1, 1, 1, 0, 1);

    // 8) MLP layer 2 (bf16x3): h1 @ w2^T + b2 -> h2 fp32
    gemm_mma<<<dim3(16, 64), 128, SMEM_GEMM>>>(
        (const __nv_bfloat16*)p_th, (const __nv_bfloat16*)p_tl,
        (const __nv_bfloat16*)p_w2h, (const __nv_bfloat16*)p_w2l,
        p_h2, nullptr, nullptr, N_PTS, DIM, DIM, b2, 0, 1, 0, 0);

    // 9) BatchNorm -> hn splits (g_sh/g_sl)
    bn_zero_kernel<<<(DIM + 255) / 256, 256>>>();
    bn_stats_kernel<<<dim3(DIM / 256, N_PTS / 256), 256>>>();
    bn_finalize_kernel<<<(DIM + 255) / 256, 256>>>(gamma, beta);
    bn_apply_kernel<<<(unsigned)(nND / 256), 256>>>();

    // 10) classifier (bf16x3): hn @ wc^T -> out [8192, 751]
    gemm_mma<<<dim3((NCLS + 127) / 128, 64), 128, SMEM_GEMM>>>(
        (const __nv_bfloat16*)p_sh, (const __nv_bfloat16*)p_sl,
        (const __nv_bfloat16*)p_wch, (const __nv_bfloat16*)p_wcl,
        out, nullptr, nullptr, N_PTS, NCLS, DIM, nullptr, 0, 1, 0, 0);
}